// round 9
// baseline (speedup 1.0000x reference)
#include <cuda_runtime.h>
#include <cuda_bf16.h>
#include <cstdint>

// Problem shape (fixed by dataset)
#define B_ROWS 1024
#define C_COLS 32768
#define D_DIM  512

// GEMM tiling
#define BM 128
#define BN 128
#define BK 32
#define SA 40            // padded smem row stride (bf16 elems); 80 B => rows stay 16B-aligned
#define NK (D_DIM / BK)  // 16

// Scratch (static device globals: allocation-free per harness rules).
__device__ __align__(16) __nv_bfloat16 g_Bn[(size_t)B_ROWS * D_DIM];
__device__ __align__(16) __nv_bfloat16 g_Pn[(size_t)C_COLS * D_DIM];
__device__ float g_rowacc[B_ROWS];
__device__ float g_pos[B_ROWS];

// ---------------------------------------------------------------------------
// Normalize embeddings -> bf16 (norm 3), zero row accumulators
// grid = 1024, block = 128
// ---------------------------------------------------------------------------
__global__ void k_norm_emb(const float* __restrict__ x) {
    int row = blockIdx.x;
    int tid = threadIdx.x;
    const float4* src = (const float4*)(x + (size_t)row * D_DIM);
    float4 v = src[tid];
    float s = v.x * v.x + v.y * v.y + v.z * v.z + v.w * v.w;
#pragma unroll
    for (int o = 16; o > 0; o >>= 1) s += __shfl_xor_sync(0xffffffffu, s, o);
    __shared__ float ss[4];
    if ((tid & 31) == 0) ss[tid >> 5] = s;
    __syncthreads();
    float tot = ss[0] + ss[1] + ss[2] + ss[3];
    float scale = 3.0f / fmaxf(sqrtf(tot), 1e-12f);
    __nv_bfloat162 p0 = __floats2bfloat162_rn(v.x * scale, v.y * scale);
    __nv_bfloat162 p1 = __floats2bfloat162_rn(v.z * scale, v.w * scale);
    __nv_bfloat162* dst = (__nv_bfloat162*)(g_Bn + (size_t)row * D_DIM + tid * 4);
    dst[0] = p0;
    dst[1] = p1;
    if (tid == 0) g_rowacc[row] = 0.0f;
}

// ---------------------------------------------------------------------------
// Normalize proxies -> bf16 (norm 3)
// grid = 32768, block = 128
// ---------------------------------------------------------------------------
__global__ void k_norm_pxy(const float* __restrict__ x) {
    int row = blockIdx.x;
    int tid = threadIdx.x;
    const float4* src = (const float4*)(x + (size_t)row * D_DIM);
    float4 v = src[tid];
    float s = v.x * v.x + v.y * v.y + v.z * v.z + v.w * v.w;
#pragma unroll
    for (int o = 16; o > 0; o >>= 1) s += __shfl_xor_sync(0xffffffffu, s, o);
    __shared__ float ss[4];
    if ((tid & 31) == 0) ss[tid >> 5] = s;
    __syncthreads();
    float tot = ss[0] + ss[1] + ss[2] + ss[3];
    float scale = 3.0f / fmaxf(sqrtf(tot), 1e-12f);
    __nv_bfloat162 p0 = __floats2bfloat162_rn(v.x * scale, v.y * scale);
    __nv_bfloat162 p1 = __floats2bfloat162_rn(v.z * scale, v.w * scale);
    __nv_bfloat162* dst = (__nv_bfloat162*)(g_Pn + (size_t)row * D_DIM + tid * 4);
    dst[0] = p0;
    dst[1] = p1;
}

// ---------------------------------------------------------------------------
// Positive distances: pos_dist[i] = 18 - 2 * dot(Bn_i, Pn_{label_i})
// Labels dtype is autodetected (int32 vs int64 storage) using only reads
// within the first 4096 bytes, which are valid under either layout.
// grid = 1024, block = 128
// ---------------------------------------------------------------------------
__global__ void k_pos(const int* __restrict__ lab32) {
    int row = blockIdx.x;
    int tid = threadIdx.x;

    // Detect layout: OR all odd int32 slots in the first 1024 words.
    // int64 storage -> these are high halves of labels < 2^15 -> all 0.
    // int32 storage -> these are 512 random labels -> OR != 0 (w.p. ~1).
    int det = 0;
    for (int j = tid; j < 512; j += 128) det |= lab32[2 * j + 1];
#pragma unroll
    for (int o = 16; o > 0; o >>= 1) det |= __shfl_xor_sync(0xffffffffu, det, o);
    __shared__ int sOr[4];
    if ((tid & 31) == 0) sOr[tid >> 5] = det;
    __syncthreads();
    int is64 = ((sOr[0] | sOr[1] | sOr[2] | sOr[3]) == 0);

    int lab = is64 ? lab32[2 * row] : lab32[row];
    lab &= (C_COLS - 1);  // hard clamp: wrong guess => wrong value, never OOB

    const __nv_bfloat162* a = (const __nv_bfloat162*)(g_Bn + (size_t)row * D_DIM);
    const __nv_bfloat162* b = (const __nv_bfloat162*)(g_Pn + (size_t)lab * D_DIM);
    float s = 0.0f;
#pragma unroll
    for (int j = 0; j < 2; j++) {
        int idx = tid * 2 + j;
        float2 fa = __bfloat1622float2(a[idx]);
        float2 fb = __bfloat1622float2(b[idx]);
        s += fa.x * fb.x + fa.y * fb.y;
    }
#pragma unroll
    for (int o = 16; o > 0; o >>= 1) s += __shfl_xor_sync(0xffffffffu, s, o);
    __shared__ float ss[4];
    if ((tid & 31) == 0) ss[tid >> 5] = s;
    __syncthreads();
    if (tid == 0) {
        float dot = ss[0] + ss[1] + ss[2] + ss[3];
        g_pos[row] = 18.0f - 2.0f * dot;
    }
}

// ---------------------------------------------------------------------------
// GEMM s = Bn @ Pn^T fused with exp(2s-18) row-sum epilogue.
// grid = (C/BN, B/BM) = (256, 8), block = 256 (8 warps, 2x4 warp grid)
// Each warp: 64x32 tile via m16n8k16 bf16 mma.sync.
// ---------------------------------------------------------------------------
__device__ __forceinline__ void cp_async16(void* sm, const void* gm) {
    uint32_t a = (uint32_t)__cvta_generic_to_shared(sm);
    asm volatile("cp.async.cg.shared.global [%0], [%1], 16;\n" ::"r"(a), "l"(gm));
}

__global__ __launch_bounds__(256, 2) void k_gemm() {
    __shared__ __align__(16) __nv_bfloat16 smA[2][BM * SA];
    __shared__ __align__(16) __nv_bfloat16 smB[2][BN * SA];
    __shared__ float red[BM];

    int tid = threadIdx.x;
    int mBase = blockIdx.y * BM;
    int nBase = blockIdx.x * BN;
    int lane = tid & 31, warp = tid >> 5;
    int g = lane >> 2, t = lane & 3;
    int wm = (warp >> 2) * 64;  // 0 or 64
    int wn = (warp & 3) * 32;   // 0..96

    float acc[4][4][4];
#pragma unroll
    for (int mt = 0; mt < 4; mt++)
#pragma unroll
        for (int nt = 0; nt < 4; nt++)
#pragma unroll
            for (int cc = 0; cc < 4; cc++) acc[mt][nt][cc] = 0.0f;

    int r = tid >> 2;        // 0..63
    int c = (tid & 3) * 8;   // 0,8,16,24

    const __nv_bfloat16* gaBase = g_Bn + (size_t)(mBase + r) * D_DIM + c;
    const __nv_bfloat16* gbBase = g_Pn + (size_t)(nBase + r) * D_DIM + c;

    // prefetch tile 0
    {
        cp_async16(&smA[0][r * SA + c], gaBase);
        cp_async16(&smA[0][(r + 64) * SA + c], gaBase + (size_t)64 * D_DIM);
        cp_async16(&smB[0][r * SA + c], gbBase);
        cp_async16(&smB[0][(r + 64) * SA + c], gbBase + (size_t)64 * D_DIM);
    }
    asm volatile("cp.async.commit_group;\n");

    for (int kk = 0; kk < NK; kk++) {
        int cur = kk & 1;
        if (kk + 1 < NK) {
            int nxt = (kk + 1) & 1;
            int ko = (kk + 1) * BK;
            cp_async16(&smA[nxt][r * SA + c], gaBase + ko);
            cp_async16(&smA[nxt][(r + 64) * SA + c], gaBase + (size_t)64 * D_DIM + ko);
            cp_async16(&smB[nxt][r * SA + c], gbBase + ko);
            cp_async16(&smB[nxt][(r + 64) * SA + c], gbBase + (size_t)64 * D_DIM + ko);
        }
        asm volatile("cp.async.commit_group;\n");
        asm volatile("cp.async.wait_group 1;\n");
        __syncthreads();

#pragma unroll
        for (int ks = 0; ks < 2; ks++) {
            int kb = ks * 16;
            uint32_t A[4][4], Bf[4][2];
#pragma unroll
            for (int mt = 0; mt < 4; mt++) {
                const __nv_bfloat16* base = &smA[cur][(wm + mt * 16 + g) * SA + kb + 2 * t];
                A[mt][0] = *(const uint32_t*)base;            // rows g,   k 0-7
                A[mt][1] = *(const uint32_t*)(base + 8 * SA); // rows g+8, k 0-7
                A[mt][2] = *(const uint32_t*)(base + 8);      // rows g,   k 8-15
                A[mt][3] = *(const uint32_t*)(base + 8 * SA + 8);
            }
#pragma unroll
            for (int nt = 0; nt < 4; nt++) {
                const __nv_bfloat16* base = &smB[cur][(wn + nt * 8 + g) * SA + kb + 2 * t];
                Bf[nt][0] = *(const uint32_t*)base;       // n g, k 0-7
                Bf[nt][1] = *(const uint32_t*)(base + 8); // n g, k 8-15
            }
#pragma unroll
            for (int mt = 0; mt < 4; mt++)
#pragma unroll
                for (int nt = 0; nt < 4; nt++) {
                    asm volatile(
                        "mma.sync.aligned.m16n8k16.row.col.f32.bf16.bf16.f32 "
                        "{%0,%1,%2,%3}, {%4,%5,%6,%7}, {%8,%9}, {%0,%1,%2,%3};\n"
                        : "+f"(acc[mt][nt][0]), "+f"(acc[mt][nt][1]),
                          "+f"(acc[mt][nt][2]), "+f"(acc[mt][nt][3])
                        : "r"(A[mt][0]), "r"(A[mt][1]), "r"(A[mt][2]), "r"(A[mt][3]),
                          "r"(Bf[nt][0]), "r"(Bf[nt][1]));
                }
        }
        __syncthreads();
    }

    // Epilogue: e = exp(2s - 18); per-row sums -> smem -> one global atomic/row
    if (tid < BM) red[tid] = 0.0f;
    __syncthreads();

    float lsum[4][2];
#pragma unroll
    for (int mt = 0; mt < 4; mt++) { lsum[mt][0] = 0.0f; lsum[mt][1] = 0.0f; }
#pragma unroll
    for (int mt = 0; mt < 4; mt++)
#pragma unroll
        for (int nt = 0; nt < 4; nt++) {
            lsum[mt][0] += __expf(fmaf(2.0f, acc[mt][nt][0], -18.0f))
                         + __expf(fmaf(2.0f, acc[mt][nt][1], -18.0f));
            lsum[mt][1] += __expf(fmaf(2.0f, acc[mt][nt][2], -18.0f))
                         + __expf(fmaf(2.0f, acc[mt][nt][3], -18.0f));
        }
#pragma unroll
    for (int mt = 0; mt < 4; mt++)
#pragma unroll
        for (int h = 0; h < 2; h++) {
            float v = lsum[mt][h];
            v += __shfl_xor_sync(0xffffffffu, v, 1);
            v += __shfl_xor_sync(0xffffffffu, v, 2);
            if (t == 0) {
                int rowLocal = wm + mt * 16 + h * 8 + g;
                atomicAdd(&red[rowLocal], v);
            }
        }
    __syncthreads();
    if (tid < BM) atomicAdd(&g_rowacc[mBase + tid], red[tid]);
}

// ---------------------------------------------------------------------------
// Finalize: loss_i = pos_dist_i + log(rowacc_i - exp(-pos_dist_i)); mean
// grid = 1, block = 1024
// ---------------------------------------------------------------------------
__global__ void k_final(float* __restrict__ out) {
    int i = threadIdx.x;
    float pd = g_pos[i];
    float negsum = g_rowacc[i] - __expf(-pd);
    float v = pd + logf(negsum);
#pragma unroll
    for (int o = 16; o > 0; o >>= 1) v += __shfl_xor_sync(0xffffffffu, v, o);
    __shared__ float ss[32];
    if ((i & 31) == 0) ss[i >> 5] = v;
    __syncthreads();
    if (i < 32) {
        float w = ss[i];
#pragma unroll
        for (int o = 16; o > 0; o >>= 1) w += __shfl_xor_sync(0xffffffffu, w, o);
        if (i == 0) out[0] = w * (1.0f / (float)B_ROWS);
    }
}

// ---------------------------------------------------------------------------
extern "C" void kernel_launch(void* const* d_in, const int* in_sizes, int n_in,
                              void* d_out, int out_size) {
    (void)out_size;
    // Bind inputs by element count, not position (sizes are pairwise distinct).
    const float* emb = nullptr;
    const float* pxy = nullptr;
    const int* lab = nullptr;
    for (int i = 0; i < n_in; i++) {
        if (in_sizes[i] == B_ROWS * D_DIM) emb = (const float*)d_in[i];
        else if (in_sizes[i] == C_COLS * D_DIM) pxy = (const float*)d_in[i];
        else lab = (const int*)d_in[i];
    }
    float* out = (float*)d_out;

    k_norm_emb<<<B_ROWS, 128>>>(emb);
    k_norm_pxy<<<C_COLS, 128>>>(pxy);
    k_pos<<<B_ROWS, 128>>>(lab);
    k_gemm<<<dim3(C_COLS / BN, B_ROWS / BM), 256>>>();
    k_final<<<1, 1024>>>(out);
}

// round 11
// speedup vs baseline: 1.1847x; 1.1847x over previous
#include <cuda_runtime.h>
#include <cuda_bf16.h>
#include <cstdint>

// Problem shape (fixed by dataset)
#define B_ROWS 1024
#define C_COLS 32768
#define D_DIM  512

// GEMM tiling
#define BM 128
#define BN 128
#define BK 64
#define SA 72            // padded smem row stride (bf16): 144 B -> 16B-aligned rows, ldmatrix conflict-free
#define NK (D_DIM / BK)  // 8

#define A_SZ (BM * SA * 2)            // 18432 B per stage
#define STAGE (2 * BM * SA * 2)       // A + B per stage = 36864 B
#define RED_OFF (2 * STAGE)           // 73728
#define SMEM_TOTAL (RED_OFF + BM * 4) // + red[BM] floats = 74240 B

// Scratch (static device globals: allocation-free per harness rules).
__device__ __align__(16) __nv_bfloat16 g_Bn[(size_t)B_ROWS * D_DIM];
__device__ __align__(16) __nv_bfloat16 g_Pn[(size_t)C_COLS * D_DIM];
__device__ float g_rowacc[B_ROWS];
__device__ float g_pos[B_ROWS];

__device__ __forceinline__ uint32_t smem_u32(const void* p) {
    uint32_t a;
    asm("{ .reg .u64 t; cvta.to.shared.u64 t, %1; cvt.u32.u64 %0, t; }" : "=r"(a) : "l"(p));
    return a;
}
__device__ __forceinline__ void cp_async16(uint32_t sm, const void* gm) {
    asm volatile("cp.async.cg.shared.global [%0], [%1], 16;\n" ::"r"(sm), "l"(gm));
}
__device__ __forceinline__ void ldm_x4(uint32_t& r0, uint32_t& r1, uint32_t& r2, uint32_t& r3,
                                       uint32_t addr) {
    asm volatile("ldmatrix.sync.aligned.m8n8.x4.shared.b16 {%0,%1,%2,%3}, [%4];"
                 : "=r"(r0), "=r"(r1), "=r"(r2), "=r"(r3)
                 : "r"(addr));
}

// ---------------------------------------------------------------------------
// Normalize embeddings -> bf16 (norm 3), zero row accumulators
// ---------------------------------------------------------------------------
__global__ void k_norm_emb(const float* __restrict__ x) {
    int row = blockIdx.x;
    int tid = threadIdx.x;
    const float4* src = (const float4*)(x + (size_t)row * D_DIM);
    float4 v = src[tid];
    float s = v.x * v.x + v.y * v.y + v.z * v.z + v.w * v.w;
#pragma unroll
    for (int o = 16; o > 0; o >>= 1) s += __shfl_xor_sync(0xffffffffu, s, o);
    __shared__ float ss[4];
    if ((tid & 31) == 0) ss[tid >> 5] = s;
    __syncthreads();
    float tot = ss[0] + ss[1] + ss[2] + ss[3];
    float scale = 3.0f / fmaxf(sqrtf(tot), 1e-12f);
    __nv_bfloat162 p0 = __floats2bfloat162_rn(v.x * scale, v.y * scale);
    __nv_bfloat162 p1 = __floats2bfloat162_rn(v.z * scale, v.w * scale);
    __nv_bfloat162* dst = (__nv_bfloat162*)(g_Bn + (size_t)row * D_DIM + tid * 4);
    dst[0] = p0;
    dst[1] = p1;
    if (tid == 0) g_rowacc[row] = 0.0f;
}

// ---------------------------------------------------------------------------
// Normalize proxies -> bf16 (norm 3)
// ---------------------------------------------------------------------------
__global__ void k_norm_pxy(const float* __restrict__ x) {
    int row = blockIdx.x;
    int tid = threadIdx.x;
    const float4* src = (const float4*)(x + (size_t)row * D_DIM);
    float4 v = src[tid];
    float s = v.x * v.x + v.y * v.y + v.z * v.z + v.w * v.w;
#pragma unroll
    for (int o = 16; o > 0; o >>= 1) s += __shfl_xor_sync(0xffffffffu, s, o);
    __shared__ float ss[4];
    if ((tid & 31) == 0) ss[tid >> 5] = s;
    __syncthreads();
    float tot = ss[0] + ss[1] + ss[2] + ss[3];
    float scale = 3.0f / fmaxf(sqrtf(tot), 1e-12f);
    __nv_bfloat162 p0 = __floats2bfloat162_rn(v.x * scale, v.y * scale);
    __nv_bfloat162 p1 = __floats2bfloat162_rn(v.z * scale, v.w * scale);
    __nv_bfloat162* dst = (__nv_bfloat162*)(g_Pn + (size_t)row * D_DIM + tid * 4);
    dst[0] = p0;
    dst[1] = p1;
}

// ---------------------------------------------------------------------------
// Positive distances with labels dtype autodetect (int32 vs int64 storage)
// ---------------------------------------------------------------------------
__global__ void k_pos(const int* __restrict__ lab32) {
    int row = blockIdx.x;
    int tid = threadIdx.x;
    int det = 0;
    for (int j = tid; j < 512; j += 128) det |= lab32[2 * j + 1];
#pragma unroll
    for (int o = 16; o > 0; o >>= 1) det |= __shfl_xor_sync(0xffffffffu, det, o);
    __shared__ int sOr[4];
    if ((tid & 31) == 0) sOr[tid >> 5] = det;
    __syncthreads();
    int is64 = ((sOr[0] | sOr[1] | sOr[2] | sOr[3]) == 0);
    int lab = is64 ? lab32[2 * row] : lab32[row];
    lab &= (C_COLS - 1);

    const __nv_bfloat162* a = (const __nv_bfloat162*)(g_Bn + (size_t)row * D_DIM);
    const __nv_bfloat162* b = (const __nv_bfloat162*)(g_Pn + (size_t)lab * D_DIM);
    float s = 0.0f;
#pragma unroll
    for (int j = 0; j < 2; j++) {
        int idx = tid * 2 + j;
        float2 fa = __bfloat1622float2(a[idx]);
        float2 fb = __bfloat1622float2(b[idx]);
        s += fa.x * fb.x + fa.y * fb.y;
    }
#pragma unroll
    for (int o = 16; o > 0; o >>= 1) s += __shfl_xor_sync(0xffffffffu, s, o);
    __shared__ float ss[4];
    if ((tid & 31) == 0) ss[tid >> 5] = s;
    __syncthreads();
    if (tid == 0) {
        float dot = ss[0] + ss[1] + ss[2] + ss[3];
        g_pos[row] = 18.0f - 2.0f * dot;
    }
}

// ---------------------------------------------------------------------------
// GEMM s = Bn @ Pn^T fused with exp(2s-18) row-sum epilogue.
// grid = (C/BN, B/BM) = (256, 8), block = 256 (8 warps, 2x4 warp grid).
// Each warp: 64x32 via m16n8k16 mma.sync; fragments fed by ldmatrix.x4.
// BK=64, 2-stage cp.async pipeline (8 mainloop iterations).
// ---------------------------------------------------------------------------
__global__ __launch_bounds__(256, 2) void k_gemm() {
    extern __shared__ __align__(16) char dsm[];
    float* red = (float*)(dsm + RED_OFF);

    int tid = threadIdx.x;
    int mBase = blockIdx.y * BM;
    int nBase = blockIdx.x * BN;
    int lane = tid & 31, warp = tid >> 5;
    int g = lane >> 2, t = lane & 3;
    int wm = (warp >> 2) * 64;  // 0 or 64
    int wn = (warp & 3) * 32;   // 0..96

    uint32_t sbase = smem_u32(dsm);

    // ldmatrix per-lane address components (verified conflict-free, SA=72)
    int aR = (lane & 7) + ((lane >> 3) & 1) * 8;  // row offset within 16-row A tile
    int aC = ((lane >> 4) & 1) * 8;               // k offset (0 or 8)
    int bR = (lane & 7) + ((lane >> 4) & 1) * 8;  // row offset within 16-row (2x nt) B group
    int bC = ((lane >> 3) & 1) * 8;               // k offset (0 or 8)

    float acc[4][4][4];
#pragma unroll
    for (int mt = 0; mt < 4; mt++)
#pragma unroll
        for (int nt = 0; nt < 4; nt++)
#pragma unroll
            for (int cc = 0; cc < 4; cc++) acc[mt][nt][cc] = 0.0f;

    int r = tid >> 3;        // 0..31 (row step 32 per 256 threads... see loop)
    int c8 = (tid & 7) * 8;  // 0..56 elems (8 cp16 per 128B row)

    const __nv_bfloat16* gA0 = g_Bn + (size_t)mBase * D_DIM;
    const __nv_bfloat16* gB0 = g_Pn + (size_t)nBase * D_DIM;

    // stage loader: k-iter kk -> stage kk&1, K offset kk*BK
    auto load_stage = [&](int kk) {
        uint32_t aB = sbase + (kk & 1) * STAGE;
        uint32_t bB = aB + A_SZ;
        int ko = kk * BK;
#pragma unroll
        for (int rr = r; rr < BM; rr += 32) {
            cp_async16(aB + (rr * SA + c8) * 2, gA0 + (size_t)rr * D_DIM + ko + c8);
            cp_async16(bB + (rr * SA + c8) * 2, gB0 + (size_t)rr * D_DIM + ko + c8);
        }
    };

    load_stage(0);
    asm volatile("cp.async.commit_group;\n");

    for (int kk = 0; kk < NK; kk++) {
        int cur = kk & 1;
        if (kk + 1 < NK) load_stage(kk + 1);
        asm volatile("cp.async.commit_group;\n");
        asm volatile("cp.async.wait_group 1;\n");
        __syncthreads();

        uint32_t aT = sbase + cur * STAGE;
        uint32_t bT = aT + A_SZ;
#pragma unroll
        for (int ks = 0; ks < 4; ks++) {
            int kb = ks * 16;
            uint32_t A[4][4], Bf[4][2];
#pragma unroll
            for (int mt = 0; mt < 4; mt++)
                ldm_x4(A[mt][0], A[mt][1], A[mt][2], A[mt][3],
                       aT + ((wm + mt * 16 + aR) * SA + kb + aC) * 2);
#pragma unroll
            for (int p = 0; p < 2; p++)
                ldm_x4(Bf[2 * p][0], Bf[2 * p][1], Bf[2 * p + 1][0], Bf[2 * p + 1][1],
                       bT + ((wn + p * 16 + bR) * SA + kb + bC) * 2);
#pragma unroll
            for (int mt = 0; mt < 4; mt++)
#pragma unroll
                for (int nt = 0; nt < 4; nt++) {
                    asm volatile(
                        "mma.sync.aligned.m16n8k16.row.col.f32.bf16.bf16.f32 "
                        "{%0,%1,%2,%3}, {%4,%5,%6,%7}, {%8,%9}, {%0,%1,%2,%3};\n"
                        : "+f"(acc[mt][nt][0]), "+f"(acc[mt][nt][1]),
                          "+f"(acc[mt][nt][2]), "+f"(acc[mt][nt][3])
                        : "r"(A[mt][0]), "r"(A[mt][1]), "r"(A[mt][2]), "r"(A[mt][3]),
                          "r"(Bf[nt][0]), "r"(Bf[nt][1]));
                }
        }
        __syncthreads();
    }

    // Epilogue: e = exp(2s - 18); per-row sums -> smem -> one global atomic/row
    if (tid < BM) red[tid] = 0.0f;
    __syncthreads();

    float lsum[4][2];
#pragma unroll
    for (int mt = 0; mt < 4; mt++) { lsum[mt][0] = 0.0f; lsum[mt][1] = 0.0f; }
#pragma unroll
    for (int mt = 0; mt < 4; mt++)
#pragma unroll
        for (int nt = 0; nt < 4; nt++) {
            lsum[mt][0] += __expf(fmaf(2.0f, acc[mt][nt][0], -18.0f))
                         + __expf(fmaf(2.0f, acc[mt][nt][1], -18.0f));
            lsum[mt][1] += __expf(fmaf(2.0f, acc[mt][nt][2], -18.0f))
                         + __expf(fmaf(2.0f, acc[mt][nt][3], -18.0f));
        }
#pragma unroll
    for (int mt = 0; mt < 4; mt++)
#pragma unroll
        for (int h = 0; h < 2; h++) {
            float v = lsum[mt][h];
            v += __shfl_xor_sync(0xffffffffu, v, 1);
            v += __shfl_xor_sync(0xffffffffu, v, 2);
            if (t == 0) atomicAdd(&red[wm + mt * 16 + h * 8 + g], v);
        }
    __syncthreads();
    if (tid < BM) atomicAdd(&g_rowacc[mBase + tid], red[tid]);
}

// ---------------------------------------------------------------------------
// Finalize: loss_i = pos_dist_i + log(rowacc_i - exp(-pos_dist_i)); mean
// ---------------------------------------------------------------------------
__global__ void k_final(float* __restrict__ out) {
    int i = threadIdx.x;
    float pd = g_pos[i];
    float negsum = g_rowacc[i] - __expf(-pd);
    float v = pd + logf(negsum);
#pragma unroll
    for (int o = 16; o > 0; o >>= 1) v += __shfl_xor_sync(0xffffffffu, v, o);
    __shared__ float ss[32];
    if ((i & 31) == 0) ss[i >> 5] = v;
    __syncthreads();
    if (i < 32) {
        float w = ss[i];
#pragma unroll
        for (int o = 16; o > 0; o >>= 1) w += __shfl_xor_sync(0xffffffffu, w, o);
        if (i == 0) out[0] = w * (1.0f / (float)B_ROWS);
    }
}

// ---------------------------------------------------------------------------
extern "C" void kernel_launch(void* const* d_in, const int* in_sizes, int n_in,
                              void* d_out, int out_size) {
    (void)out_size;
    const float* emb = nullptr;
    const float* pxy = nullptr;
    const int* lab = nullptr;
    for (int i = 0; i < n_in; i++) {
        if (in_sizes[i] == B_ROWS * D_DIM) emb = (const float*)d_in[i];
        else if (in_sizes[i] == C_COLS * D_DIM) pxy = (const float*)d_in[i];
        else lab = (const int*)d_in[i];
    }
    float* out = (float*)d_out;

    static bool attr_done = false;
    if (!attr_done) {
        cudaFuncSetAttribute(k_gemm, cudaFuncAttributeMaxDynamicSharedMemorySize, SMEM_TOTAL);
        attr_done = true;
    }

    k_norm_emb<<<B_ROWS, 128>>>(emb);
    k_norm_pxy<<<C_COLS, 128>>>(pxy);
    k_pos<<<B_ROWS, 128>>>(lab);
    k_gemm<<<dim3(C_COLS / BN, B_ROWS / BM), 256, SMEM_TOTAL>>>();
    k_final<<<1, 1024>>>(out);
}

// round 12
// speedup vs baseline: 1.2457x; 1.0514x over previous
#include <cuda_runtime.h>
#include <cuda_bf16.h>
#include <cstdint>

// Problem shape (fixed by dataset)
#define B_ROWS 1024
#define C_COLS 32768
#define D_DIM  512

// GEMM tiling
#define BM 128
#define BN 128
#define BK 64
#define SA 72            // padded smem row stride (bf16): 144 B -> 16B-aligned rows, ldmatrix conflict-free
#define NK (D_DIM / BK)  // 8
#define NSTAGE 3

#define A_SZ (BM * SA * 2)            // 18432 B per stage
#define STAGE (2 * BM * SA * 2)       // A + B per stage = 36864 B
#define RED_OFF (NSTAGE * STAGE)      // 110592
#define SMEM_TOTAL (RED_OFF + BM * 4) // + red[BM] floats = 111104 B

// Scratch (static device globals: allocation-free per harness rules).
__device__ __align__(16) __nv_bfloat16 g_Bn[(size_t)B_ROWS * D_DIM];
__device__ __align__(16) __nv_bfloat16 g_Pn[(size_t)C_COLS * D_DIM];
__device__ float g_rowacc[B_ROWS];
__device__ float g_pos[B_ROWS];

__device__ __forceinline__ uint32_t smem_u32(const void* p) {
    uint32_t a;
    asm("{ .reg .u64 t; cvta.to.shared.u64 t, %1; cvt.u32.u64 %0, t; }" : "=r"(a) : "l"(p));
    return a;
}
__device__ __forceinline__ void cp_async16(uint32_t sm, const void* gm) {
    asm volatile("cp.async.cg.shared.global [%0], [%1], 16;\n" ::"r"(sm), "l"(gm));
}
__device__ __forceinline__ void ldm_x4(uint32_t& r0, uint32_t& r1, uint32_t& r2, uint32_t& r3,
                                       uint32_t addr) {
    asm volatile("ldmatrix.sync.aligned.m8n8.x4.shared.b16 {%0,%1,%2,%3}, [%4];"
                 : "=r"(r0), "=r"(r1), "=r"(r2), "=r"(r3)
                 : "r"(addr));
}

// ---------------------------------------------------------------------------
// Normalize embeddings -> bf16 (norm 3), zero row accumulators
// ---------------------------------------------------------------------------
__global__ void k_norm_emb(const float* __restrict__ x) {
    int row = blockIdx.x;
    int tid = threadIdx.x;
    const float4* src = (const float4*)(x + (size_t)row * D_DIM);
    float4 v = src[tid];
    float s = v.x * v.x + v.y * v.y + v.z * v.z + v.w * v.w;
#pragma unroll
    for (int o = 16; o > 0; o >>= 1) s += __shfl_xor_sync(0xffffffffu, s, o);
    __shared__ float ss[4];
    if ((tid & 31) == 0) ss[tid >> 5] = s;
    __syncthreads();
    float tot = ss[0] + ss[1] + ss[2] + ss[3];
    float scale = 3.0f / fmaxf(sqrtf(tot), 1e-12f);
    __nv_bfloat162 p0 = __floats2bfloat162_rn(v.x * scale, v.y * scale);
    __nv_bfloat162 p1 = __floats2bfloat162_rn(v.z * scale, v.w * scale);
    __nv_bfloat162* dst = (__nv_bfloat162*)(g_Bn + (size_t)row * D_DIM + tid * 4);
    dst[0] = p0;
    dst[1] = p1;
    if (tid == 0) g_rowacc[row] = 0.0f;
}

// ---------------------------------------------------------------------------
// Normalize proxies -> bf16 (norm 3)
// ---------------------------------------------------------------------------
__global__ void k_norm_pxy(const float* __restrict__ x) {
    int row = blockIdx.x;
    int tid = threadIdx.x;
    const float4* src = (const float4*)(x + (size_t)row * D_DIM);
    float4 v = src[tid];
    float s = v.x * v.x + v.y * v.y + v.z * v.z + v.w * v.w;
#pragma unroll
    for (int o = 16; o > 0; o >>= 1) s += __shfl_xor_sync(0xffffffffu, s, o);
    __shared__ float ss[4];
    if ((tid & 31) == 0) ss[tid >> 5] = s;
    __syncthreads();
    float tot = ss[0] + ss[1] + ss[2] + ss[3];
    float scale = 3.0f / fmaxf(sqrtf(tot), 1e-12f);
    __nv_bfloat162 p0 = __floats2bfloat162_rn(v.x * scale, v.y * scale);
    __nv_bfloat162 p1 = __floats2bfloat162_rn(v.z * scale, v.w * scale);
    __nv_bfloat162* dst = (__nv_bfloat162*)(g_Pn + (size_t)row * D_DIM + tid * 4);
    dst[0] = p0;
    dst[1] = p1;
}

// ---------------------------------------------------------------------------
// Positive distances with labels dtype autodetect (int32 vs int64 storage)
// ---------------------------------------------------------------------------
__global__ void k_pos(const int* __restrict__ lab32) {
    int row = blockIdx.x;
    int tid = threadIdx.x;
    int det = 0;
    for (int j = tid; j < 512; j += 128) det |= lab32[2 * j + 1];
#pragma unroll
    for (int o = 16; o > 0; o >>= 1) det |= __shfl_xor_sync(0xffffffffu, det, o);
    __shared__ int sOr[4];
    if ((tid & 31) == 0) sOr[tid >> 5] = det;
    __syncthreads();
    int is64 = ((sOr[0] | sOr[1] | sOr[2] | sOr[3]) == 0);
    int lab = is64 ? lab32[2 * row] : lab32[row];
    lab &= (C_COLS - 1);

    const __nv_bfloat162* a = (const __nv_bfloat162*)(g_Bn + (size_t)row * D_DIM);
    const __nv_bfloat162* b = (const __nv_bfloat162*)(g_Pn + (size_t)lab * D_DIM);
    float s = 0.0f;
#pragma unroll
    for (int j = 0; j < 2; j++) {
        int idx = tid * 2 + j;
        float2 fa = __bfloat1622float2(a[idx]);
        float2 fb = __bfloat1622float2(b[idx]);
        s += fa.x * fb.x + fa.y * fb.y;
    }
#pragma unroll
    for (int o = 16; o > 0; o >>= 1) s += __shfl_xor_sync(0xffffffffu, s, o);
    __shared__ float ss[4];
    if ((tid & 31) == 0) ss[tid >> 5] = s;
    __syncthreads();
    if (tid == 0) {
        float dot = ss[0] + ss[1] + ss[2] + ss[3];
        g_pos[row] = 18.0f - 2.0f * dot;
    }
}

// ---------------------------------------------------------------------------
// GEMM s = Bn @ Pn^T fused with exp(2s-18) row-sum epilogue.
// grid = (C/BN, B/BM) = (256, 8), block = 256 (8 warps, 2x4 warp grid).
// Each warp: 64x32 via m16n8k16 mma.sync; fragments fed by ldmatrix.x4.
// BK=64, 3-stage cp.async pipeline, ONE barrier per k-iteration:
//   at iter kk, load_stage(kk+2) overwrites the stage read at iter kk-1,
//   and the data-ready __syncthreads() of iter kk already proves all warps
//   finished iter kk-1's compute -> no trailing barrier needed.
// ---------------------------------------------------------------------------
__global__ __launch_bounds__(256, 2) void k_gemm() {
    extern __shared__ __align__(16) char dsm[];
    float* red = (float*)(dsm + RED_OFF);

    int tid = threadIdx.x;
    int mBase = blockIdx.y * BM;
    int nBase = blockIdx.x * BN;
    int lane = tid & 31, warp = tid >> 5;
    int g = lane >> 2, t = lane & 3;
    int wm = (warp >> 2) * 64;  // 0 or 64
    int wn = (warp & 3) * 32;   // 0..96

    uint32_t sbase = smem_u32(dsm);

    // ldmatrix per-lane address components (conflict-free with SA=72)
    int aR = (lane & 7) + ((lane >> 3) & 1) * 8;
    int aC = ((lane >> 4) & 1) * 8;
    int bR = (lane & 7) + ((lane >> 4) & 1) * 8;
    int bC = ((lane >> 3) & 1) * 8;

    float acc[4][4][4];
#pragma unroll
    for (int mt = 0; mt < 4; mt++)
#pragma unroll
        for (int nt = 0; nt < 4; nt++)
#pragma unroll
            for (int cc = 0; cc < 4; cc++) acc[mt][nt][cc] = 0.0f;

    int r = tid >> 3;        // 0..31
    int c8 = (tid & 7) * 8;  // 0..56 elems

    const __nv_bfloat16* gA0 = g_Bn + (size_t)mBase * D_DIM;
    const __nv_bfloat16* gB0 = g_Pn + (size_t)nBase * D_DIM;

    // stage loader: k-iter kk -> stage kk % 3, K offset kk*BK
    auto load_stage = [&](int kk) {
        uint32_t aB = sbase + (kk % NSTAGE) * STAGE;
        uint32_t bB = aB + A_SZ;
        int ko = kk * BK;
#pragma unroll
        for (int rr = r; rr < BM; rr += 32) {
            cp_async16(aB + (rr * SA + c8) * 2, gA0 + (size_t)rr * D_DIM + ko + c8);
            cp_async16(bB + (rr * SA + c8) * 2, gB0 + (size_t)rr * D_DIM + ko + c8);
        }
    };

    load_stage(0);
    asm volatile("cp.async.commit_group;\n");
    load_stage(1);
    asm volatile("cp.async.commit_group;\n");

    for (int kk = 0; kk < NK; kk++) {
        asm volatile("cp.async.wait_group 1;\n");  // group kk complete
        __syncthreads();                           // stage kk visible; iter kk-1 compute done

        if (kk + 2 < NK) load_stage(kk + 2);       // overwrites stage read at iter kk-1: safe
        asm volatile("cp.async.commit_group;\n");  // commit (possibly empty) to keep counts uniform

        uint32_t aT = sbase + (kk % NSTAGE) * STAGE;
        uint32_t bT = aT + A_SZ;
#pragma unroll
        for (int ks = 0; ks < 4; ks++) {
            int kb = ks * 16;
            uint32_t A[4][4], Bf[4][2];
#pragma unroll
            for (int mt = 0; mt < 4; mt++)
                ldm_x4(A[mt][0], A[mt][1], A[mt][2], A[mt][3],
                       aT + ((wm + mt * 16 + aR) * SA + kb + aC) * 2);
#pragma unroll
            for (int p = 0; p < 2; p++)
                ldm_x4(Bf[2 * p][0], Bf[2 * p][1], Bf[2 * p + 1][0], Bf[2 * p + 1][1],
                       bT + ((wn + p * 16 + bR) * SA + kb + bC) * 2);
#pragma unroll
            for (int mt = 0; mt < 4; mt++)
#pragma unroll
                for (int nt = 0; nt < 4; nt++) {
                    asm volatile(
                        "mma.sync.aligned.m16n8k16.row.col.f32.bf16.bf16.f32 "
                        "{%0,%1,%2,%3}, {%4,%5,%6,%7}, {%8,%9}, {%0,%1,%2,%3};\n"
                        : "+f"(acc[mt][nt][0]), "+f"(acc[mt][nt][1]),
                          "+f"(acc[mt][nt][2]), "+f"(acc[mt][nt][3])
                        : "r"(A[mt][0]), "r"(A[mt][1]), "r"(A[mt][2]), "r"(A[mt][3]),
                          "r"(Bf[nt][0]), "r"(Bf[nt][1]));
                }
        }
    }

    // Epilogue: e = exp(2s - 18); per-row sums -> smem -> one global atomic/row
    __syncthreads();  // all compute done before red[] init
    if (tid < BM) red[tid] = 0.0f;
    __syncthreads();

    float lsum[4][2];
#pragma unroll
    for (int mt = 0; mt < 4; mt++) { lsum[mt][0] = 0.0f; lsum[mt][1] = 0.0f; }
#pragma unroll
    for (int mt = 0; mt < 4; mt++)
#pragma unroll
        for (int nt = 0; nt < 4; nt++) {
            lsum[mt][0] += __expf(fmaf(2.0f, acc[mt][nt][0], -18.0f))
                         + __expf(fmaf(2.0f, acc[mt][nt][1], -18.0f));
            lsum[mt][1] += __expf(fmaf(2.0f, acc[mt][nt][2], -18.0f))
                         + __expf(fmaf(2.0f, acc[mt][nt][3], -18.0f));
        }
#pragma unroll
    for (int mt = 0; mt < 4; mt++)
#pragma unroll
        for (int h = 0; h < 2; h++) {
            float v = lsum[mt][h];
            v += __shfl_xor_sync(0xffffffffu, v, 1);
            v += __shfl_xor_sync(0xffffffffu, v, 2);
            if (t == 0) atomicAdd(&red[wm + mt * 16 + h * 8 + g], v);
        }
    __syncthreads();
    if (tid < BM) atomicAdd(&g_rowacc[mBase + tid], red[tid]);
}

// ---------------------------------------------------------------------------
// Finalize: loss_i = pos_dist_i + log(rowacc_i - exp(-pos_dist_i)); mean
// ---------------------------------------------------------------------------
__global__ void k_final(float* __restrict__ out) {
    int i = threadIdx.x;
    float pd = g_pos[i];
    float negsum = g_rowacc[i] - __expf(-pd);
    float v = pd + logf(negsum);
#pragma unroll
    for (int o = 16; o > 0; o >>= 1) v += __shfl_xor_sync(0xffffffffu, v, o);
    __shared__ float ss[32];
    if ((i & 31) == 0) ss[i >> 5] = v;
    __syncthreads();
    if (i < 32) {
        float w = ss[i];
#pragma unroll
        for (int o = 16; o > 0; o >>= 1) w += __shfl_xor_sync(0xffffffffu, w, o);
        if (i == 0) out[0] = w * (1.0f / (float)B_ROWS);
    }
}

// ---------------------------------------------------------------------------
extern "C" void kernel_launch(void* const* d_in, const int* in_sizes, int n_in,
                              void* d_out, int out_size) {
    (void)out_size;
    const float* emb = nullptr;
    const float* pxy = nullptr;
    const int* lab = nullptr;
    for (int i = 0; i < n_in; i++) {
        if (in_sizes[i] == B_ROWS * D_DIM) emb = (const float*)d_in[i];
        else if (in_sizes[i] == C_COLS * D_DIM) pxy = (const float*)d_in[i];
        else lab = (const int*)d_in[i];
    }
    float* out = (float*)d_out;

    static bool attr_done = false;
    if (!attr_done) {
        cudaFuncSetAttribute(k_gemm, cudaFuncAttributeMaxDynamicSharedMemorySize, SMEM_TOTAL);
        attr_done = true;
    }

    k_norm_emb<<<B_ROWS, 128>>>(emb);
    k_norm_pxy<<<C_COLS, 128>>>(pxy);
    k_pos<<<B_ROWS, 128>>>(lab);
    k_gemm<<<dim3(C_COLS / BN, B_ROWS / BM), 256, SMEM_TOTAL>>>();
    k_final<<<1, 1024>>>(out);
}